// round 15
// baseline (speedup 1.0000x reference)
#include <cuda_runtime.h>
#include <cuda_bf16.h>

#define G   500
#define DN  128
#define DE  64
#define DG  128
#define DO  128

// ---------------------------------------------------------------------------
// FINAL — converged. Five healthy-hold measurements: 82.66/82.69/82.66/83.07/
// 82.66 us at 6.22-6.24 TB/s (DRAM ~79%). 512 MB of mandatory single-touch
// reads at the chip's path-independent LTS throughput cap; no bytes
// removable, no faster path exists (cap identical for LDG and TMA).
// Alternatives tested and rejected: kernel splits (113-158us),
// slicing+atomics (129us), warp-split streams (84.4us), deferred reductions
// (84.4us), __ldcs (83.4us).
//
// Structure: one block per graph — block-local offset reduce over the length
// arrays, float4-coalesced streaming of node + edge rows, smem tree
// reduction to per-graph means, in-block projection of the 128 outputs.
// ---------------------------------------------------------------------------
__global__ __launch_bounds__(512) void fused_kernel(const float4* __restrict__ nf4,
                                                    const float4* __restrict__ ef4,
                                                    const float*  __restrict__ gf,
                                                    const float*  __restrict__ Wn,
                                                    const float*  __restrict__ We,
                                                    const float*  __restrict__ Wg,
                                                    const float*  __restrict__ bias,
                                                    const int*    __restrict__ nn,
                                                    const int*    __restrict__ ne,
                                                    float*        __restrict__ out) {
    __shared__ float4 red[512];
    __shared__ float  nagg_s[DN];
    __shared__ float  eagg_s[DE];
    __shared__ int    sint[34];   // [0..15] node partials, [16..31] edge
                                  // partials, [32] node total, [33] edge total

    const int g    = blockIdx.x;
    const int tid  = threadIdx.x;
    const int lane = tid & 31;
    const int w    = tid >> 5;

    // ---- offsets: sum lengths[0..g) for nodes and edges (G <= 512) ----
    int pn = 0, pe = 0;
    if (tid < g) { pn = nn[tid]; pe = ne[tid]; }
    #pragma unroll
    for (int d = 16; d; d >>= 1) {
        pn += __shfl_xor_sync(0xffffffffu, pn, d);
        pe += __shfl_xor_sync(0xffffffffu, pe, d);
    }
    if (lane == 0) { sint[w] = pn; sint[16 + w] = pe; }
    __syncthreads();
    // stage 2: warps 0/1 reduce the 16 partials; results go to DEDICATED
    // slots 32/33 (disjoint from the partials being read -> no race).
    if (w == 0) {
        int a = (lane < 16) ? sint[lane] : 0;
        #pragma unroll
        for (int d = 8; d; d >>= 1) a += __shfl_xor_sync(0xffffffffu, a, d);
        if (lane == 0) sint[32] = a;
    } else if (w == 1) {
        int a = (lane < 16) ? sint[16 + lane] : 0;
        #pragma unroll
        for (int d = 8; d; d >>= 1) a += __shfl_xor_sync(0xffffffffu, a, d);
        if (lane == 0) sint[33] = a;
    }
    __syncthreads();
    const int noff = sint[32];
    const int eoff = sint[33];
    const int ncnt = nn[g];
    const int ecnt = ne[g];

    // ---- node streaming: 32 float4 cols x 16 row-groups ----
    {
        const float4* base = nf4 + (size_t)noff * 32 + lane;
        float4 acc = make_float4(0.f, 0.f, 0.f, 0.f);
        #pragma unroll 4
        for (int r = w; r < ncnt; r += 16) {
            float4 v = base[(size_t)r * 32];
            acc.x += v.x; acc.y += v.y; acc.z += v.z; acc.w += v.w;
        }
        red[w * 32 + lane] = acc;
        __syncthreads();
        #pragma unroll
        for (int s = 8; s >= 1; s >>= 1) {
            if (w < s) {
                float4 o = red[(w + s) * 32 + lane];
                float4 m = red[w * 32 + lane];
                m.x += o.x; m.y += o.y; m.z += o.z; m.w += o.w;
                red[w * 32 + lane] = m;
            }
            __syncthreads();
        }
        if (w == 0) {
            const float inv = 1.0f / (float)max(ncnt, 1);
            float4 m = red[lane];
            nagg_s[lane * 4 + 0] = m.x * inv;
            nagg_s[lane * 4 + 1] = m.y * inv;
            nagg_s[lane * 4 + 2] = m.z * inv;
            nagg_s[lane * 4 + 3] = m.w * inv;
        }
        __syncthreads();
    }

    // ---- edge streaming: 16 float4 cols x 32 row-groups ----
    {
        const int col = tid & 15;
        const int rg  = tid >> 4;
        const float4* base = ef4 + (size_t)eoff * 16 + col;
        float4 acc = make_float4(0.f, 0.f, 0.f, 0.f);
        #pragma unroll 4
        for (int r = rg; r < ecnt; r += 32) {
            float4 v = base[(size_t)r * 16];
            acc.x += v.x; acc.y += v.y; acc.z += v.z; acc.w += v.w;
        }
        red[rg * 16 + col] = acc;
        __syncthreads();
        #pragma unroll
        for (int s = 16; s >= 1; s >>= 1) {
            if (rg < s) {
                float4 o = red[(rg + s) * 16 + col];
                float4 m = red[rg * 16 + col];
                m.x += o.x; m.y += o.y; m.z += o.z; m.w += o.w;
                red[rg * 16 + col] = m;
            }
            __syncthreads();
        }
        if (rg == 0) {
            const float inv = 1.0f / (float)max(ecnt, 1);
            float4 m = red[col];
            eagg_s[col * 4 + 0] = m.x * inv;
            eagg_s[col * 4 + 1] = m.y * inv;
            eagg_s[col * 4 + 2] = m.z * inv;
            eagg_s[col * 4 + 3] = m.w * inv;
        }
        __syncthreads();
    }

    // ---- projection: 16 warps x 8 outputs each ----
    const float* gfr = gf + (size_t)g * DG;
    for (int o = w; o < DO; o += 16) {
        float s = 0.f;
        const float* wn = Wn + o * DN;
        #pragma unroll
        for (int k = 0; k < DN / 32; k++) s += nagg_s[lane + 32 * k] * wn[lane + 32 * k];
        const float* we = We + o * DE;
        #pragma unroll
        for (int k = 0; k < DE / 32; k++) s += eagg_s[lane + 32 * k] * we[lane + 32 * k];
        const float* wgp = Wg + o * DG;
        #pragma unroll
        for (int k = 0; k < DG / 32; k++) s += gfr[lane + 32 * k] * wgp[lane + 32 * k];
        #pragma unroll
        for (int d = 16; d; d >>= 1) s += __shfl_xor_sync(0xffffffffu, s, d);
        if (lane == 0) out[(size_t)g * DO + o] = s + bias[o];
    }
}

// ---------------------------------------------------------------------------
extern "C" void kernel_launch(void* const* d_in, const int* in_sizes, int n_in,
                              void* d_out, int out_size) {
    const float* node_features = (const float*)d_in[0];   // [N, 128]
    const float* edge_features = (const float*)d_in[1];   // [E, 64]
    const float* global_feats  = (const float*)d_in[2];   // [G, 128]
    const float* W_node        = (const float*)d_in[3];   // [128, 128]
    const float* W_edges       = (const float*)d_in[4];   // [128, 64]
    const float* W_global      = (const float*)d_in[5];   // [128, 128]
    const float* bias          = (const float*)d_in[6];   // [128]
    const int*   num_nodes     = (const int*)d_in[7];     // [G]
    const int*   num_edges     = (const int*)d_in[8];     // [G]
    float*       out           = (float*)d_out;           // [G, 128]

    fused_kernel<<<G, 512>>>((const float4*)node_features,
                             (const float4*)edge_features,
                             global_feats, W_node, W_edges, W_global, bias,
                             num_nodes, num_edges, out);
}

// round 16
// speedup vs baseline: 1.0066x; 1.0066x over previous
#include <cuda_runtime.h>
#include <cuda_bf16.h>

#define G   500
#define DN  128
#define DE  64
#define DG  128
#define DO  128

// ---------------------------------------------------------------------------
// FINAL — converged. Six healthy-hold measurements: 82.66/82.69/82.66/83.07/
// 82.66/82.98 us at 6.16-6.24 TB/s (DRAM ~78-79%). 512 MB of mandatory
// single-touch reads at the chip's path-independent LTS throughput cap.
// Average-vs-instantaneous bandwidth gap bounds the grid-quantization tail
// at <1us; no harvesting scheme beats its own overhead. Alternatives tested
// and rejected: kernel splits (113-158us), slicing+atomics (129us),
// warp-split streams (84.4us), deferred reductions (84.4us), __ldcs (83.4us).
//
// Structure: one block per graph — block-local offset reduce over the length
// arrays, float4-coalesced streaming of node + edge rows, smem tree
// reduction to per-graph means, in-block projection of the 128 outputs.
// ---------------------------------------------------------------------------
__global__ __launch_bounds__(512) void fused_kernel(const float4* __restrict__ nf4,
                                                    const float4* __restrict__ ef4,
                                                    const float*  __restrict__ gf,
                                                    const float*  __restrict__ Wn,
                                                    const float*  __restrict__ We,
                                                    const float*  __restrict__ Wg,
                                                    const float*  __restrict__ bias,
                                                    const int*    __restrict__ nn,
                                                    const int*    __restrict__ ne,
                                                    float*        __restrict__ out) {
    __shared__ float4 red[512];
    __shared__ float  nagg_s[DN];
    __shared__ float  eagg_s[DE];
    __shared__ int    sint[34];   // [0..15] node partials, [16..31] edge
                                  // partials, [32] node total, [33] edge total

    const int g    = blockIdx.x;
    const int tid  = threadIdx.x;
    const int lane = tid & 31;
    const int w    = tid >> 5;

    // ---- offsets: sum lengths[0..g) for nodes and edges (G <= 512) ----
    int pn = 0, pe = 0;
    if (tid < g) { pn = nn[tid]; pe = ne[tid]; }
    #pragma unroll
    for (int d = 16; d; d >>= 1) {
        pn += __shfl_xor_sync(0xffffffffu, pn, d);
        pe += __shfl_xor_sync(0xffffffffu, pe, d);
    }
    if (lane == 0) { sint[w] = pn; sint[16 + w] = pe; }
    __syncthreads();
    // stage 2: warps 0/1 reduce the 16 partials; results go to DEDICATED
    // slots 32/33 (disjoint from the partials being read -> no race).
    if (w == 0) {
        int a = (lane < 16) ? sint[lane] : 0;
        #pragma unroll
        for (int d = 8; d; d >>= 1) a += __shfl_xor_sync(0xffffffffu, a, d);
        if (lane == 0) sint[32] = a;
    } else if (w == 1) {
        int a = (lane < 16) ? sint[16 + lane] : 0;
        #pragma unroll
        for (int d = 8; d; d >>= 1) a += __shfl_xor_sync(0xffffffffu, a, d);
        if (lane == 0) sint[33] = a;
    }
    __syncthreads();
    const int noff = sint[32];
    const int eoff = sint[33];
    const int ncnt = nn[g];
    const int ecnt = ne[g];

    // ---- node streaming: 32 float4 cols x 16 row-groups ----
    {
        const float4* base = nf4 + (size_t)noff * 32 + lane;
        float4 acc = make_float4(0.f, 0.f, 0.f, 0.f);
        #pragma unroll 4
        for (int r = w; r < ncnt; r += 16) {
            float4 v = base[(size_t)r * 32];
            acc.x += v.x; acc.y += v.y; acc.z += v.z; acc.w += v.w;
        }
        red[w * 32 + lane] = acc;
        __syncthreads();
        #pragma unroll
        for (int s = 8; s >= 1; s >>= 1) {
            if (w < s) {
                float4 o = red[(w + s) * 32 + lane];
                float4 m = red[w * 32 + lane];
                m.x += o.x; m.y += o.y; m.z += o.z; m.w += o.w;
                red[w * 32 + lane] = m;
            }
            __syncthreads();
        }
        if (w == 0) {
            const float inv = 1.0f / (float)max(ncnt, 1);
            float4 m = red[lane];
            nagg_s[lane * 4 + 0] = m.x * inv;
            nagg_s[lane * 4 + 1] = m.y * inv;
            nagg_s[lane * 4 + 2] = m.z * inv;
            nagg_s[lane * 4 + 3] = m.w * inv;
        }
        __syncthreads();
    }

    // ---- edge streaming: 16 float4 cols x 32 row-groups ----
    {
        const int col = tid & 15;
        const int rg  = tid >> 4;
        const float4* base = ef4 + (size_t)eoff * 16 + col;
        float4 acc = make_float4(0.f, 0.f, 0.f, 0.f);
        #pragma unroll 4
        for (int r = rg; r < ecnt; r += 32) {
            float4 v = base[(size_t)r * 16];
            acc.x += v.x; acc.y += v.y; acc.z += v.z; acc.w += v.w;
        }
        red[rg * 16 + col] = acc;
        __syncthreads();
        #pragma unroll
        for (int s = 16; s >= 1; s >>= 1) {
            if (rg < s) {
                float4 o = red[(rg + s) * 16 + col];
                float4 m = red[rg * 16 + col];
                m.x += o.x; m.y += o.y; m.z += o.z; m.w += o.w;
                red[rg * 16 + col] = m;
            }
            __syncthreads();
        }
        if (rg == 0) {
            const float inv = 1.0f / (float)max(ecnt, 1);
            float4 m = red[col];
            eagg_s[col * 4 + 0] = m.x * inv;
            eagg_s[col * 4 + 1] = m.y * inv;
            eagg_s[col * 4 + 2] = m.z * inv;
            eagg_s[col * 4 + 3] = m.w * inv;
        }
        __syncthreads();
    }

    // ---- projection: 16 warps x 8 outputs each ----
    const float* gfr = gf + (size_t)g * DG;
    for (int o = w; o < DO; o += 16) {
        float s = 0.f;
        const float* wn = Wn + o * DN;
        #pragma unroll
        for (int k = 0; k < DN / 32; k++) s += nagg_s[lane + 32 * k] * wn[lane + 32 * k];
        const float* we = We + o * DE;
        #pragma unroll
        for (int k = 0; k < DE / 32; k++) s += eagg_s[lane + 32 * k] * we[lane + 32 * k];
        const float* wgp = Wg + o * DG;
        #pragma unroll
        for (int k = 0; k < DG / 32; k++) s += gfr[lane + 32 * k] * wgp[lane + 32 * k];
        #pragma unroll
        for (int d = 16; d; d >>= 1) s += __shfl_xor_sync(0xffffffffu, s, d);
        if (lane == 0) out[(size_t)g * DO + o] = s + bias[o];
    }
}

// ---------------------------------------------------------------------------
extern "C" void kernel_launch(void* const* d_in, const int* in_sizes, int n_in,
                              void* d_out, int out_size) {
    const float* node_features = (const float*)d_in[0];   // [N, 128]
    const float* edge_features = (const float*)d_in[1];   // [E, 64]
    const float* global_feats  = (const float*)d_in[2];   // [G, 128]
    const float* W_node        = (const float*)d_in[3];   // [128, 128]
    const float* W_edges       = (const float*)d_in[4];   // [128, 64]
    const float* W_global      = (const float*)d_in[5];   // [128, 128]
    const float* bias          = (const float*)d_in[6];   // [128]
    const int*   num_nodes     = (const int*)d_in[7];     // [G]
    const int*   num_edges     = (const int*)d_in[8];     // [G]
    float*       out           = (float*)d_out;           // [G, 128]

    fused_kernel<<<G, 512>>>((const float4*)node_features,
                             (const float4*)edge_features,
                             global_feats, W_node, W_edges, W_global, bias,
                             num_nodes, num_edges, out);
}

// round 17
// speedup vs baseline: 1.0070x; 1.0004x over previous
#include <cuda_runtime.h>
#include <cuda_bf16.h>

#define G   500
#define DN  128
#define DE  64
#define DG  128
#define DO  128

// ---------------------------------------------------------------------------
// FINAL — converged. Seven healthy-hold measurements: 82.43-83.07 us at
// 6.16-6.29 TB/s (DRAM ~78-79%); wall time tracks per-hold DVFS, not code.
// 512 MB of mandatory single-touch reads at the chip's path-independent LTS
// throughput cap. Average-vs-instantaneous bandwidth gap bounds the
// grid-quantization tail at <1us; no harvesting scheme beats its overhead.
// Alternatives tested and rejected: kernel splits (113-158us),
// slicing+atomics (129us), warp-split streams (84.4us), deferred reductions
// (84.4us), __ldcs (83.4us).
//
// Structure: one block per graph — block-local offset reduce over the length
// arrays, float4-coalesced streaming of node + edge rows, smem tree
// reduction to per-graph means, in-block projection of the 128 outputs.
// ---------------------------------------------------------------------------
__global__ __launch_bounds__(512) void fused_kernel(const float4* __restrict__ nf4,
                                                    const float4* __restrict__ ef4,
                                                    const float*  __restrict__ gf,
                                                    const float*  __restrict__ Wn,
                                                    const float*  __restrict__ We,
                                                    const float*  __restrict__ Wg,
                                                    const float*  __restrict__ bias,
                                                    const int*    __restrict__ nn,
                                                    const int*    __restrict__ ne,
                                                    float*        __restrict__ out) {
    __shared__ float4 red[512];
    __shared__ float  nagg_s[DN];
    __shared__ float  eagg_s[DE];
    __shared__ int    sint[34];   // [0..15] node partials, [16..31] edge
                                  // partials, [32] node total, [33] edge total

    const int g    = blockIdx.x;
    const int tid  = threadIdx.x;
    const int lane = tid & 31;
    const int w    = tid >> 5;

    // ---- offsets: sum lengths[0..g) for nodes and edges (G <= 512) ----
    int pn = 0, pe = 0;
    if (tid < g) { pn = nn[tid]; pe = ne[tid]; }
    #pragma unroll
    for (int d = 16; d; d >>= 1) {
        pn += __shfl_xor_sync(0xffffffffu, pn, d);
        pe += __shfl_xor_sync(0xffffffffu, pe, d);
    }
    if (lane == 0) { sint[w] = pn; sint[16 + w] = pe; }
    __syncthreads();
    // stage 2: warps 0/1 reduce the 16 partials; results go to DEDICATED
    // slots 32/33 (disjoint from the partials being read -> no race).
    if (w == 0) {
        int a = (lane < 16) ? sint[lane] : 0;
        #pragma unroll
        for (int d = 8; d; d >>= 1) a += __shfl_xor_sync(0xffffffffu, a, d);
        if (lane == 0) sint[32] = a;
    } else if (w == 1) {
        int a = (lane < 16) ? sint[16 + lane] : 0;
        #pragma unroll
        for (int d = 8; d; d >>= 1) a += __shfl_xor_sync(0xffffffffu, a, d);
        if (lane == 0) sint[33] = a;
    }
    __syncthreads();
    const int noff = sint[32];
    const int eoff = sint[33];
    const int ncnt = nn[g];
    const int ecnt = ne[g];

    // ---- node streaming: 32 float4 cols x 16 row-groups ----
    {
        const float4* base = nf4 + (size_t)noff * 32 + lane;
        float4 acc = make_float4(0.f, 0.f, 0.f, 0.f);
        #pragma unroll 4
        for (int r = w; r < ncnt; r += 16) {
            float4 v = base[(size_t)r * 32];
            acc.x += v.x; acc.y += v.y; acc.z += v.z; acc.w += v.w;
        }
        red[w * 32 + lane] = acc;
        __syncthreads();
        #pragma unroll
        for (int s = 8; s >= 1; s >>= 1) {
            if (w < s) {
                float4 o = red[(w + s) * 32 + lane];
                float4 m = red[w * 32 + lane];
                m.x += o.x; m.y += o.y; m.z += o.z; m.w += o.w;
                red[w * 32 + lane] = m;
            }
            __syncthreads();
        }
        if (w == 0) {
            const float inv = 1.0f / (float)max(ncnt, 1);
            float4 m = red[lane];
            nagg_s[lane * 4 + 0] = m.x * inv;
            nagg_s[lane * 4 + 1] = m.y * inv;
            nagg_s[lane * 4 + 2] = m.z * inv;
            nagg_s[lane * 4 + 3] = m.w * inv;
        }
        __syncthreads();
    }

    // ---- edge streaming: 16 float4 cols x 32 row-groups ----
    {
        const int col = tid & 15;
        const int rg  = tid >> 4;
        const float4* base = ef4 + (size_t)eoff * 16 + col;
        float4 acc = make_float4(0.f, 0.f, 0.f, 0.f);
        #pragma unroll 4
        for (int r = rg; r < ecnt; r += 32) {
            float4 v = base[(size_t)r * 16];
            acc.x += v.x; acc.y += v.y; acc.z += v.z; acc.w += v.w;
        }
        red[rg * 16 + col] = acc;
        __syncthreads();
        #pragma unroll
        for (int s = 16; s >= 1; s >>= 1) {
            if (rg < s) {
                float4 o = red[(rg + s) * 16 + col];
                float4 m = red[rg * 16 + col];
                m.x += o.x; m.y += o.y; m.z += o.z; m.w += o.w;
                red[rg * 16 + col] = m;
            }
            __syncthreads();
        }
        if (rg == 0) {
            const float inv = 1.0f / (float)max(ecnt, 1);
            float4 m = red[col];
            eagg_s[col * 4 + 0] = m.x * inv;
            eagg_s[col * 4 + 1] = m.y * inv;
            eagg_s[col * 4 + 2] = m.z * inv;
            eagg_s[col * 4 + 3] = m.w * inv;
        }
        __syncthreads();
    }

    // ---- projection: 16 warps x 8 outputs each ----
    const float* gfr = gf + (size_t)g * DG;
    for (int o = w; o < DO; o += 16) {
        float s = 0.f;
        const float* wn = Wn + o * DN;
        #pragma unroll
        for (int k = 0; k < DN / 32; k++) s += nagg_s[lane + 32 * k] * wn[lane + 32 * k];
        const float* we = We + o * DE;
        #pragma unroll
        for (int k = 0; k < DE / 32; k++) s += eagg_s[lane + 32 * k] * we[lane + 32 * k];
        const float* wgp = Wg + o * DG;
        #pragma unroll
        for (int k = 0; k < DG / 32; k++) s += gfr[lane + 32 * k] * wgp[lane + 32 * k];
        #pragma unroll
        for (int d = 16; d; d >>= 1) s += __shfl_xor_sync(0xffffffffu, s, d);
        if (lane == 0) out[(size_t)g * DO + o] = s + bias[o];
    }
}

// ---------------------------------------------------------------------------
extern "C" void kernel_launch(void* const* d_in, const int* in_sizes, int n_in,
                              void* d_out, int out_size) {
    const float* node_features = (const float*)d_in[0];   // [N, 128]
    const float* edge_features = (const float*)d_in[1];   // [E, 64]
    const float* global_feats  = (const float*)d_in[2];   // [G, 128]
    const float* W_node        = (const float*)d_in[3];   // [128, 128]
    const float* W_edges       = (const float*)d_in[4];   // [128, 64]
    const float* W_global      = (const float*)d_in[5];   // [128, 128]
    const float* bias          = (const float*)d_in[6];   // [128]
    const int*   num_nodes     = (const int*)d_in[7];     // [G]
    const int*   num_edges     = (const int*)d_in[8];     // [G]
    float*       out           = (float*)d_out;           // [G, 128]

    fused_kernel<<<G, 512>>>((const float4*)node_features,
                             (const float4*)edge_features,
                             global_feats, W_node, W_edges, W_global, bias,
                             num_nodes, num_edges, out);
}